// round 17
// baseline (speedup 1.0000x reference)
#include <cuda_runtime.h>
#include <math.h>

#define BB 4
#define NN 512
#define DD 1024
#define EE 8
#define HH 4096
#define RR 32            // candidate rows: (b in 0..3) x (n in 0..7)
#define OUT_ELEMS (BB*NN*DD)

#define S1_SPLITS 32     // stage1 d-splits (32 d each)
#define S2_SPLITS 128    // stage2 j-splits (32 j each)
#define S1_BLOCKS (32 * S1_SPLITS)          // 1024
#define S2_BLOCKS (8 * S2_SPLITS)           // 1024
#define GATE_BLOCKS 512
#define ZERO_BLOCKS 512                      // 512 * 128thr * 8 float4 = 8 MB out
#define OACC_BLOCKS 8                        // 8 * 128thr * 8 float4 = 128 KB oacc
#define S2_TICKETS (S2_BLOCKS + 1)           // 1024 stage2 + 1 loss = 1025
#define EPI_BLOCKS 32                        // last 32 tickets run the epilogue

typedef unsigned long long ull;

// ---------------- device scratch (zero at load; each call restores zeros) -------
__device__ int          g_flag[RR];      // reset by loss block after reading
__device__ float        g_gate0[RR];     // fully rewritten every call
__device__ float        g_gs[RR];        // fully rewritten every call
__device__ float        g_hacc[RR*HH];   // zeroed by this call's epilogue
__device__ float        g_oacc[RR*DD];   // zeroed by next call's launch 1
__device__ unsigned int g_counter;       // zeroed by next call's launch 1

// ---------------- packed fp32x2 + REDG helpers ----------------
__device__ __forceinline__ void fma2(ull& d, ull a, ull b) {
    asm("fma.rn.f32x2 %0, %1, %2, %0;" : "+l"(d) : "l"(a), "l"(b));
}
__device__ __forceinline__ void unpack2(ull v, float& lo, float& hi) {
    asm("mov.b64 {%0, %1}, %2;" : "=f"(lo), "=f"(hi) : "l"(v));
}
__device__ __forceinline__ void redg_add_v4(float* p, float a, float b, float c, float d) {
    asm volatile("red.global.add.v4.f32 [%0], {%1, %2, %3, %4};"
                 :: "l"(p), "f"(a), "f"(b), "f"(c), "f"(d) : "memory");
}

__device__ __forceinline__ int row_x_off(int r) {
    return ((r >> 3) * NN + (r & 7)) * DD;
}

// ---------------- gate block body (128 threads: 4 warps x 1 token) ----------------
// Reads w_gate [D,E] directly: per lane, rows 4*d4..4*d4+3 are one contiguous
// 128-byte stripe (8 float4) -> coalesced, L1/L2-resident after first block.
__device__ void gate_block(const float* __restrict__ x,
                           const float* __restrict__ w_gate,
                           const float* __restrict__ b_gate,
                           int gblk, int t) {
    int warp = t >> 5, lane = t & 31;
    int tok = gblk * 4 + warp;               // 512 gate blocks * 4 = 2048 tokens

    float acc[8];
#pragma unroll
    for (int e = 0; e < 8; e++) acc[e] = 0.f;

    const float4* xp = reinterpret_cast<const float4*>(x + (size_t)tok * DD) + lane;
#pragma unroll
    for (int i = 0; i < 8; i++) {
        int d4 = i * 32 + lane;              // float4 index into x; d = 4*d4
        float4 xv = xp[i * 32];
        const float4* wr = reinterpret_cast<const float4*>(w_gate) + (size_t)d4 * 8;
        float4 w0 = wr[0], w1 = wr[1];       // row d+0: e 0..3, 4..7
        float4 w2 = wr[2], w3 = wr[3];       // row d+1
        float4 w4 = wr[4], w5 = wr[5];       // row d+2
        float4 w6 = wr[6], w7 = wr[7];       // row d+3
        acc[0] += xv.x * w0.x + xv.y * w2.x + xv.z * w4.x + xv.w * w6.x;
        acc[1] += xv.x * w0.y + xv.y * w2.y + xv.z * w4.y + xv.w * w6.y;
        acc[2] += xv.x * w0.z + xv.y * w2.z + xv.z * w4.z + xv.w * w6.z;
        acc[3] += xv.x * w0.w + xv.y * w2.w + xv.z * w4.w + xv.w * w6.w;
        acc[4] += xv.x * w1.x + xv.y * w3.x + xv.z * w5.x + xv.w * w7.x;
        acc[5] += xv.x * w1.y + xv.y * w3.y + xv.z * w5.y + xv.w * w7.y;
        acc[6] += xv.x * w1.z + xv.y * w3.z + xv.z * w5.z + xv.w * w7.z;
        acc[7] += xv.x * w1.w + xv.y * w3.w + xv.z * w5.w + xv.w * w7.w;
    }
#pragma unroll
    for (int e = 0; e < 8; e++)
#pragma unroll
        for (int off = 16; off > 0; off >>= 1)
            acc[e] += __shfl_xor_sync(0xffffffffu, acc[e], off);

    if (lane == 0) {
        float l[8];
#pragma unroll
        for (int e = 0; e < 8; e++) l[e] = acc[e] + b_gate[e];
        int am = 0; float mx = l[0];
#pragma unroll
        for (int e = 1; e < 8; e++) if (l[e] > mx) { mx = l[e]; am = e; }
        int b = tok >> 9;
        int n = tok & 511;
        g_flag[b * 8 + am] = 1;              // benign race: writers all store 1
        if (n < 8) {
            float s = 0.f, p0 = 0.f;
#pragma unroll
            for (int e = 0; e < 8; e++) {
                float t2 = expf(l[e] - mx);
                s += t2;
                if (e == 0) p0 = t2;
            }
            g_gate0[b * 8 + n] = p0 / s;
        }
    }
}

// ---------------- launch 1: stage1 GEMM ⊕ gate ⊕ zero out[] ⊕ zero oacc/counter -----
// blocks [0,1024): stage1; [1024,1536): gate; [1536,2048): zero out; [2048,2056): oacc.
__global__ void __launch_bounds__(128) stage1_gate_kernel(const float* __restrict__ x,
                                                          const float* __restrict__ w1,
                                                          const float* __restrict__ w_gate,
                                                          const float* __restrict__ b_gate,
                                                          float* __restrict__ out) {
    int blk = blockIdx.x;
    int t = threadIdx.x;
    if (blk >= S1_BLOCKS + GATE_BLOCKS + ZERO_BLOCKS) {   // ---- zero oacc + counter ----
        int zb = blk - (S1_BLOCKS + GATE_BLOCKS + ZERO_BLOCKS);
        if (zb == 0 && t == 0) g_counter = 0;
        float4 z = make_float4(0.f, 0.f, 0.f, 0.f);
        float4* o4 = reinterpret_cast<float4*>(g_oacc);
        int base = zb * 1024 + t;                         // 8 blocks * 1024 = 8192 float4
#pragma unroll
        for (int q = 0; q < 8; q++) o4[base + 128 * q] = z;
        return;
    }
    if (blk >= S1_BLOCKS + GATE_BLOCKS) {                 // ---- zero out[] (8 MB) ----
        int zt = (blk - S1_BLOCKS - GATE_BLOCKS) * 128 + t;
        float4 z = make_float4(0.f, 0.f, 0.f, 0.f);
        float4* o4 = reinterpret_cast<float4*>(out);
#pragma unroll
        for (int q = 0; q < 8; q++) o4[zt + 65536 * q] = z;
        return;
    }
    if (blk >= S1_BLOCKS) {                               // ---- gate ----
        gate_block(x, w_gate, b_gate, blk - S1_BLOCKS, t);
        return;
    }

    // ---- stage1 GEMM: hacc += x[32,1024] @ w1[0] ----
    __shared__ float2 xs[RR][32];            // splatted x tile, 8 KB
    int jb = (blk & 31) * 128;
    int db = (blk >> 5) * 32;

#pragma unroll
    for (int q = 0; q < 8; q++) {
        int idx = t + 128 * q;               // 1024 entries
        int row = idx >> 5, dd = idx & 31;
        float v = x[row_x_off(row) + db + dd];
        xs[row][dd] = make_float2(v, v);
    }
    __syncthreads();

    int lane = t & 31, w = t >> 5;
    int rbase = w * 8;

    ull acc[8][2];
#pragma unroll
    for (int r = 0; r < 8; r++) { acc[r][0] = 0ULL; acc[r][1] = 0ULL; }

    const float* wb = w1 + (size_t)db * HH + jb + lane * 4;
    ulonglong2 p0a = *reinterpret_cast<const ulonglong2*>(wb + 0 * HH);
    ulonglong2 p0b = *reinterpret_cast<const ulonglong2*>(wb + 1 * HH);
    ulonglong2 p1a = *reinterpret_cast<const ulonglong2*>(wb + 2 * HH);
    ulonglong2 p1b = *reinterpret_cast<const ulonglong2*>(wb + 3 * HH);

#pragma unroll 4
    for (int dp = 0; dp < 16; dp++) {
        ulonglong2 ca = p0a, cb = p0b;
        p0a = p1a; p0b = p1b;
        if (dp < 14) {
            p1a = *reinterpret_cast<const ulonglong2*>(wb + (size_t)(2 * dp + 4) * HH);
            p1b = *reinterpret_cast<const ulonglong2*>(wb + (size_t)(2 * dp + 5) * HH);
        }
#pragma unroll
        for (int r = 0; r < 8; r++) {
            ulonglong2 xv = *reinterpret_cast<const ulonglong2*>(&xs[rbase + r][2 * dp]);
            fma2(acc[r][0], xv.x, ca.x);
            fma2(acc[r][1], xv.x, ca.y);
            fma2(acc[r][0], xv.y, cb.x);
            fma2(acc[r][1], xv.y, cb.y);
        }
    }
#pragma unroll
    for (int r = 0; r < 8; r++) {
        float a, b, c, d;
        unpack2(acc[r][0], a, b);
        unpack2(acc[r][1], c, d);
        redg_add_v4(&g_hacc[(size_t)(rbase + r) * HH + jb + lane * 4], a, b, c, d);
    }
}

// ---------------- score_loss body (warp 0 of the loss block) ----------------
__device__ void score_loss_block(float* __restrict__ out, int i) {
    float m = g_flag[i] ? g_gate0[i] : 0.f;
    g_flag[i] = 0;                           // restore zero-invariant for next call
    float s = m;
    s += __shfl_xor_sync(0xffffffffu, s, 8);
    s += __shfl_xor_sync(0xffffffffu, s, 16);
    float gs = m / (s + 1e-6f) * 4.0f;       // capacity = 4
    g_gs[i] = gs;

    float imp = gs;
    imp += __shfl_xor_sync(0xffffffffu, imp, 8);
    imp += __shfl_xor_sync(0xffffffffu, imp, 16);
    float ld = m > 0.f ? 1.f : 0.f;          // flag && gate0>0  (gate0>0 always)
    ld += __shfl_xor_sync(0xffffffffu, ld, 8);
    ld += __shfl_xor_sync(0xffffffffu, ld, 16);

    float s1 = (i < 8) ? imp       : 0.f;
    float s2 = (i < 8) ? imp * imp : 0.f;
    float s3 = (i < 8) ? ld        : 0.f;
    float s4 = (i < 8) ? ld * ld   : 0.f;
#pragma unroll
    for (int off = 16; off > 0; off >>= 1) {
        s1 += __shfl_xor_sync(0xffffffffu, s1, off);
        s2 += __shfl_xor_sync(0xffffffffu, s2, off);
        s3 += __shfl_xor_sync(0xffffffffu, s3, off);
        s4 += __shfl_xor_sync(0xffffffffu, s4, off);
    }
    if (i == 0) {
        const float NEL = (float)(NN * EE);
        float m1 = s1 / NEL;
        float v1 = (s2 - s1 * s1 / NEL) / (NEL - 1.f);
        float m2 = s3 / NEL;
        float v2 = (s4 - s3 * s3 / NEL) / (NEL - 1.f);
        out[OUT_ELEMS] = v1 / (m1 * m1 + 1e-10f) + v2 / (m2 * m2 + 1e-10f);
    }
}

// ---------------- launch 2: stage2 GEMM ⊕ loss ⊕ last-blocks epilogue --------------
// blocks [0,1024): stage2 (GELU(hacc+b1) inline); block 1024: score/loss.
// Every block fences + takes a ticket; the last EPI_BLOCKS tickets spin until all
// 1025 arrive, then write the scaled candidate rows and zero hacc for the next call.
__global__ void __launch_bounds__(128) stage2_loss_kernel(const float* __restrict__ w2,
                                                          const float* __restrict__ b1,
                                                          const float* __restrict__ b2,
                                                          float* __restrict__ out) {
    __shared__ float2 hs[RR][32];            // 8 KB (also used to pad loss block)
    __shared__ unsigned int tk;
    int blk = blockIdx.x;
    int t = threadIdx.x;

    if (blk == S2_BLOCKS) {                  // ---- score/loss block ----
        if (t < 32) score_loss_block(out, t);
        __threadfence();
        __syncthreads();
        if (t == 0) atomicAdd(&g_counter, 1);
        return;
    }

    // ---- stage2 GEMM: oacc += gelu(hacc+b1)[32,4096] @ w2[0] ----
    int dbt = (blk & 7) * 128;
    int jb  = (blk >> 3) * 32;

    const float kgelu = 0.70710678118654752440f;
#pragma unroll
    for (int q = 0; q < 8; q++) {
        int idx = t + 128 * q;
        int row = idx >> 5, jj = idx & 31;
        float v = g_hacc[row * HH + jb + jj] + b1[jb + jj];
        v = 0.5f * v * (1.0f + erff(v * kgelu));
        hs[row][jj] = make_float2(v, v);
    }
    __syncthreads();

    int lane = t & 31, w = t >> 5;
    int rbase = w * 8;

    ull acc[8][2];
#pragma unroll
    for (int r = 0; r < 8; r++) { acc[r][0] = 0ULL; acc[r][1] = 0ULL; }

    const float* wb = w2 + (size_t)jb * DD + dbt + lane * 4;
    ulonglong2 p0a = *reinterpret_cast<const ulonglong2*>(wb + 0 * DD);
    ulonglong2 p0b = *reinterpret_cast<const ulonglong2*>(wb + 1 * DD);
    ulonglong2 p1a = *reinterpret_cast<const ulonglong2*>(wb + 2 * DD);
    ulonglong2 p1b = *reinterpret_cast<const ulonglong2*>(wb + 3 * DD);

#pragma unroll 4
    for (int jp = 0; jp < 16; jp++) {
        ulonglong2 ca = p0a, cb = p0b;
        p0a = p1a; p0b = p1b;
        if (jp < 14) {
            p1a = *reinterpret_cast<const ulonglong2*>(wb + (size_t)(2 * jp + 4) * DD);
            p1b = *reinterpret_cast<const ulonglong2*>(wb + (size_t)(2 * jp + 5) * DD);
        }
#pragma unroll
        for (int r = 0; r < 8; r++) {
            ulonglong2 hv = *reinterpret_cast<const ulonglong2*>(&hs[rbase + r][2 * jp]);
            fma2(acc[r][0], hv.x, ca.x);
            fma2(acc[r][1], hv.x, ca.y);
            fma2(acc[r][0], hv.y, cb.x);
            fma2(acc[r][1], hv.y, cb.y);
        }
    }
#pragma unroll
    for (int r = 0; r < 8; r++) {
        float a, b, c, d;
        unpack2(acc[r][0], a, b);
        unpack2(acc[r][1], c, d);
        redg_add_v4(&g_oacc[(size_t)(rbase + r) * DD + dbt + lane * 4], a, b, c, d);
    }

    // ---- ticket + epilogue ----
    __threadfence();
    __syncthreads();
    if (t == 0) tk = atomicAdd(&g_counter, 1);
    __syncthreads();
    unsigned int ticket = tk;
    if (ticket >= S2_TICKETS - EPI_BLOCKS) {
        if (t == 0) {
            volatile unsigned int* cp = &g_counter;
            while (*cp < S2_TICKETS) __nanosleep(64);
        }
        __syncthreads();
        __threadfence();                     // acquire: see all REDGs + g_gs
        int r = ticket - (S2_TICKETS - EPI_BLOCKS);   // 0..31: candidate row
        float gs = g_gs[r];
        const float4* oa = reinterpret_cast<const float4*>(&g_oacc[r * DD]);
        const float4* bb = reinterpret_cast<const float4*>(b2);
        float4* op = reinterpret_cast<float4*>(&out[row_x_off(r)]);
#pragma unroll
        for (int q = 0; q < 2; q++) {
            int idx = t + 128 * q;           // 256 float4 per row
            float4 v = oa[idx];
            float4 bv = bb[idx];
            float4 o;
            o.x = gs * (v.x + bv.x); o.y = gs * (v.y + bv.y);
            o.z = gs * (v.z + bv.z); o.w = gs * (v.w + bv.w);
            op[idx] = o;
        }
        // zero hacc row r for the next call (1024 float4)
        float4 z = make_float4(0.f, 0.f, 0.f, 0.f);
        float4* hz = reinterpret_cast<float4*>(&g_hacc[(size_t)r * HH]);
#pragma unroll
        for (int q = 0; q < 8; q++) hz[t + 128 * q] = z;
    }
}

// ---------------- launch (2 kernels, single stream, no allocations) ----------------
extern "C" void kernel_launch(void* const* d_in, const int* in_sizes, int n_in,
                              void* d_out, int out_size) {
    const float* x      = (const float*)d_in[0];
    const float* w_gate = (const float*)d_in[1];
    const float* b_gate = (const float*)d_in[2];
    const float* w1     = (const float*)d_in[3];
    const float* b1     = (const float*)d_in[4];
    const float* w2     = (const float*)d_in[5];
    const float* b2     = (const float*)d_in[6];
    float* out = (float*)d_out;

    stage1_gate_kernel<<<S1_BLOCKS + GATE_BLOCKS + ZERO_BLOCKS + OACC_BLOCKS, 128>>>(
        x, w1, w_gate, b_gate, out);
    stage2_loss_kernel<<<S2_BLOCKS + 1, 128>>>(w2, b1, b2, out);
}